// round 11
// baseline (speedup 1.0000x reference)
#include <cuda_runtime.h>
#include <cuda_bf16.h>
#include <cstdint>

// Problem constants
#define BDIM   16
#define DDIM   256
#define TDIM   4096
#define NTOK   (BDIM * TDIM)   // 65536
#define NEMB   1024
#define NBOOKS 8

#define NEG_INF (-3.0e38f)
#define DELTA   1.0e-2f        // margin >> 6-sigma of dropped-term error

// Scratch
__device__ float g_resid[NTOK * DDIM];                  // 64 MB residual (N, D)
__device__ float g_cn[NBOOKS * NEMB];                   // 0.5*||e||^2
// Pre-split bf16 codebooks (hi only), row-major [book][emb][k=256]
__device__ __nv_bfloat16 g_bh[NBOOKS * NEMB * DDIM];    // 4 MB

// ---------------------------------------------------------------------------
// helpers
// ---------------------------------------------------------------------------
__device__ __forceinline__ uint32_t smem_u32(const void* p) {
    uint32_t a;
    asm("{ .reg .u64 t; cvta.to.shared.u64 t, %1; cvt.u32.u64 %0, t; }" : "=r"(a) : "l"(p));
    return a;
}

#define LDSM4(r, addr)                                                         \
    asm volatile("ldmatrix.sync.aligned.m8n8.x4.shared.b16 {%0,%1,%2,%3}, [%4];" \
        : "=r"((r)[0]), "=r"((r)[1]), "=r"((r)[2]), "=r"((r)[3]) : "r"(addr))

#define MMA_BF16(d, a, b0, b1)                                                 \
    asm volatile("mma.sync.aligned.m16n8k16.row.col.f32.bf16.bf16.f32 "        \
        "{%0,%1,%2,%3}, {%4,%5,%6,%7}, {%8,%9}, {%0,%1,%2,%3};"                \
        : "+f"((d)[0]), "+f"((d)[1]), "+f"((d)[2]), "+f"((d)[3])               \
        : "r"((a)[0]), "r"((a)[1]), "r"((a)[2]), "r"((a)[3]), "r"(b0), "r"(b1))

#define CP16(dst, src) asm volatile("cp.async.cg.shared.global [%0], [%1], 16;" :: "r"(dst), "l"(src))
#define CP_COMMIT()    asm volatile("cp.async.commit_group;" ::: "memory")
#define CP_WAIT1()     asm volatile("cp.async.wait_group 1;" ::: "memory")
#define CP_WAIT0()     asm volatile("cp.async.wait_group 0;" ::: "memory")

// bf16 hi/lo split of a float pair, packed low-first (consecutive k)
__device__ __forceinline__ void splitpack(float a, float b, uint32_t& hi, uint32_t& lo) {
    __nv_bfloat16 ah = __float2bfloat16(a), bh = __float2bfloat16(b);
    __nv_bfloat16 al = __float2bfloat16(a - __bfloat162float(ah));
    __nv_bfloat16 bl = __float2bfloat16(b - __bfloat162float(bh));
    __nv_bfloat162 h2; h2.x = ah; h2.y = bh;
    __nv_bfloat162 l2; l2.x = al; l2.y = bl;
    hi = *reinterpret_cast<uint32_t*>(&h2);
    lo = *reinterpret_cast<uint32_t*>(&l2);
}
__device__ __forceinline__ uint32_t pack_bf16(float a, float b) {
    __nv_bfloat162 h2; h2.x = __float2bfloat16(a); h2.y = __float2bfloat16(b);
    return *reinterpret_cast<uint32_t*>(&h2);
}

__device__ __forceinline__ void top2_merge(float& v1, int& i1, float& v2,
                                           float ov1, int oi1, float ov2) {
    if (ov1 > v1) { v2 = fmaxf(v1, ov2); v1 = ov1; i1 = oi1; }
    else          { v2 = fmaxf(v2, ov1); }
}

// ---------------------------------------------------------------------------
// transpose init / finish kernels (proven)
// ---------------------------------------------------------------------------
__global__ void init_resid(const float* __restrict__ z) {
    __shared__ float tile[32][33];
    const int b = blockIdx.z, d0 = blockIdx.y * 32, t0 = blockIdx.x * 32;
    const int tx = threadIdx.x, ty = threadIdx.y;
#pragma unroll
    for (int j = 0; j < 32; j += 8)
        tile[ty + j][tx] = z[(b * DDIM + d0 + ty + j) * TDIM + t0 + tx];
    __syncthreads();
#pragma unroll
    for (int j = 0; j < 32; j += 8)
        g_resid[(b * TDIM + t0 + ty + j) * DDIM + d0 + tx] = tile[tx][ty + j];
}

__global__ void write_out(const float* __restrict__ z, float* __restrict__ out) {
    __shared__ float tile[32][33];
    const int b = blockIdx.z, d0 = blockIdx.y * 32, t0 = blockIdx.x * 32;
    const int tx = threadIdx.x, ty = threadIdx.y;
#pragma unroll
    for (int j = 0; j < 32; j += 8)
        tile[ty + j][tx] = g_resid[(b * TDIM + t0 + ty + j) * DDIM + d0 + tx];
    __syncthreads();
#pragma unroll
    for (int j = 0; j < 32; j += 8) {
        int zi = (b * DDIM + d0 + ty + j) * TDIM + t0 + tx;
        out[zi] = z[zi] - tile[tx][ty + j];
    }
}

// per-embedding half squared norms + bf16 hi pack (1 warp = 1 embed row)
__global__ void prep_books(const float* __restrict__ books) {
    const int row  = blockIdx.x * 8 + (threadIdx.x >> 5);   // 0..8191
    const int lane = threadIdx.x & 31;
    const float4* er4 = (const float4*)(books + (size_t)row * DDIM);
    float4 v0 = er4[lane * 2];
    float4 v1 = er4[lane * 2 + 1];
    float s = v0.x*v0.x + v0.y*v0.y + v0.z*v0.z + v0.w*v0.w
            + v1.x*v1.x + v1.y*v1.y + v1.z*v1.z + v1.w*v1.w;
#pragma unroll
    for (int off = 16; off; off >>= 1) s += __shfl_xor_sync(0xffffffffu, s, off);
    if (lane == 0) g_cn[row] = 0.5f * s;

    uint4 H;
    H.x = pack_bf16(v0.x, v0.y);
    H.y = pack_bf16(v0.z, v0.w);
    H.z = pack_bf16(v1.x, v1.y);
    H.w = pack_bf16(v1.z, v1.w);
    *(uint4*)(g_bh + (size_t)row * DDIM + lane * 8) = H;
}

// ---------------------------------------------------------------------------
// Fused VQ step on mma.sync (HMMA): 2-term bf16-split GEMM + argmax + fallback
//   score ~= Ah*Bh + Al*Bh  (B-lo term dropped; margin fallback covers it)
// 512 threads = 16 warps (4 token-rows x 4 embed-cols). CTA: 128 tok x 128 emb.
// ---------------------------------------------------------------------------
// smem byte layout.  A: 4 k-chunks of [128 rows][8 x 16B granules, swizzled]
#define OFF_AH   0                 // 64 KB
#define OFF_AL   65536             // 64 KB
#define OFF_B    131072            // 2 bufs x 16KB (hi only)
#define OFF_CN   163840            // 128 f
#define OFF_V1   164352            // 512 f
#define OFF_V2   166400            // 512 f
#define OFF_I1   168448            // 512 i
#define OFF_BI   170496            // 128 i
#define OFF_UNC  171008            // 4 + 128 i
#define OFF_SR   171536            // 256 f
#define OFF_RV   172560            // 512 f
#define OFF_RI   174608            // 512 i
#define SMEM_TC  176656

#define NTHREADS 512

__device__ __forceinline__ void copy_b_chunk(uint32_t sbase, int book, int nt,
                                             int kc, int buf, int tid) {
    const __nv_bfloat16* srcH = g_bh + ((size_t)(book * NEMB + nt * 128) * DDIM + kc * 64);
#pragma unroll
    for (int u = 0; u < 2; u++) {
        int idx = tid + u * NTHREADS;     // 1024 granules: 128 rows x 8
        int r = idx >> 3, g = idx & 7;
        uint32_t dst = sbase + OFF_B + buf * 16384 + r * 128 + ((g ^ (r & 7)) << 4);
        CP16(dst, srcH + (size_t)r * DDIM + g * 8);
    }
}

__global__ void __launch_bounds__(NTHREADS) vq_step_mma(const float* __restrict__ books,
                                                        const int* __restrict__ nbu,
                                                        int book) {
    if (book >= *nbu) return;
    extern __shared__ char smem[];
    const uint32_t sbase = smem_u32(smem);
    const int tid = threadIdx.x, lane = tid & 31, wid = tid >> 5;
    const int wr = wid & 3, wc = wid >> 2;           // 4 x 4 warp grid
    const int gid = lane >> 2, tg = lane & 3;
    const int tok0 = blockIdx.x * 128;

    float* sCn  = (float*)(smem + OFF_CN);
    float* sV1  = (float*)(smem + OFF_V1);
    float* sV2  = (float*)(smem + OFF_V2);
    int*   sI1  = (int*)(smem + OFF_I1);
    int*   sBI  = (int*)(smem + OFF_BI);
    int*   sUnN = (int*)(smem + OFF_UNC);
    int*   sUn  = (int*)(smem + OFF_UNC + 4);
    float* sR   = (float*)(smem + OFF_SR);
    float* sRV  = (float*)(smem + OFF_RV);
    int*   sRI  = (int*)(smem + OFF_RI);

    if (tid == 0) *sUnN = 0;

    // ---- stage A: residual 128 tok x 256 k, split to bf16 hi/lo, swizzled ----
#pragma unroll 4
    for (int u = 0; u < 8; u++) {
        int idx = tid + u * NTHREADS;     // 4096 16B-units: 128 rows x 32
        int t = idx >> 5, gg = idx & 31;  // gg = k granule 0..31
        const float4* rr = (const float4*)(g_resid + (size_t)(tok0 + t) * DDIM);
        float4 a = rr[gg * 2], b = rr[gg * 2 + 1];
        uint4 H, L;
        splitpack(a.x, a.y, H.x, L.x);
        splitpack(a.z, a.w, H.y, L.y);
        splitpack(b.x, b.y, H.z, L.z);
        splitpack(b.z, b.w, H.w, L.w);
        int kc = gg >> 3, g = gg & 7;
        uint32_t off = kc * 16384 + t * 128 + ((g ^ (t & 7)) << 4);
        *(uint4*)(smem + OFF_AH + off) = H;
        *(uint4*)(smem + OFF_AL + off) = L;
    }
    __syncthreads();

    const float* cnb = g_cn + book * NEMB;

    // ldmatrix per-lane address components
    const int xsw = lane & 7;
    const int kg  = lane >> 4;
    const uint32_t aBase0 = sbase + OFF_AH + (wr * 32 +      (lane & 15)) * 128;
    const uint32_t aBase1 = sbase + OFF_AH + (wr * 32 + 16 + (lane & 15)) * 128;
    const uint32_t nb0 = (wc * 32 +      (lane & 15)) * 128;
    const uint32_t nb1 = (wc * 32 + 16 + (lane & 15)) * 128;

    float tv1[4], tv2[4];
    int   ti1[4];
#pragma unroll
    for (int s = 0; s < 4; s++) { tv1[s] = NEG_INF; tv2[s] = NEG_INF; ti1[s] = 0; }

    for (int nt = 0; nt < 8; nt++) {
        if (tid < 128) sCn[tid] = cnb[nt * 128 + tid];

        float acc[2][4][4];
#pragma unroll
        for (int mi = 0; mi < 2; mi++)
#pragma unroll
            for (int ni = 0; ni < 4; ni++)
#pragma unroll
                for (int q = 0; q < 4; q++) acc[mi][ni][q] = 0.f;

        copy_b_chunk(sbase, book, nt, 0, 0, tid);
        CP_COMMIT();

        for (int kc = 0; kc < 4; kc++) {
            if (kc < 3) {
                copy_b_chunk(sbase, book, nt, kc + 1, (kc + 1) & 1, tid);
                CP_COMMIT();
                CP_WAIT1();
            } else {
                CP_WAIT0();
            }
            __syncthreads();

            const uint32_t Akc = kc * 16384;
            const uint32_t Bb  = sbase + OFF_B + (kc & 1) * 16384;

#pragma unroll
            for (int ks = 0; ks < 4; ks++) {
                const int gsw = ((ks * 2 + kg) ^ xsw) << 4;
                uint32_t ah[2][4], al[2][4], bh[2][4];
                LDSM4(ah[0], aBase0 + Akc + gsw);
                LDSM4(bh[0], Bb + nb0 + gsw);
                LDSM4(bh[1], Bb + nb1 + gsw);
                LDSM4(ah[1], aBase1 + Akc + gsw);
                LDSM4(al[0], aBase0 + 65536 + Akc + gsw);   // OFF_AL = OFF_AH + 65536
                LDSM4(al[1], aBase1 + 65536 + Akc + gsw);

                // term-major: 8 independent MMAs per term
#pragma unroll
                for (int mi = 0; mi < 2; mi++)
#pragma unroll
                    for (int nb = 0; nb < 2; nb++)
#pragma unroll
                        for (int h = 0; h < 2; h++)
                            MMA_BF16(acc[mi][nb * 2 + h], ah[mi], bh[nb][h], bh[nb][h + 2]);
#pragma unroll
                for (int mi = 0; mi < 2; mi++)
#pragma unroll
                    for (int nb = 0; nb < 2; nb++)
#pragma unroll
                        for (int h = 0; h < 2; h++)
                            MMA_BF16(acc[mi][nb * 2 + h], al[mi], bh[nb][h], bh[nb][h + 2]);
            }
            __syncthreads();
        }

        // fold this nt's 32 scores/thread into per-row running top-2
#pragma unroll
        for (int mi = 0; mi < 2; mi++)
#pragma unroll
            for (int h = 0; h < 2; h++) {
                const int slot = mi * 2 + h;
#pragma unroll
                for (int ni = 0; ni < 4; ni++)
#pragma unroll
                    for (int c = 0; c < 2; c++) {
                        const int col = ni * 8 + tg * 2 + c;
                        float s = acc[mi][ni][h * 2 + c] - sCn[wc * 32 + col];
                        int  ii = nt * 128 + wc * 32 + col;
                        if (s > tv1[slot]) { tv2[slot] = tv1[slot]; tv1[slot] = s; ti1[slot] = ii; }
                        else if (s > tv2[slot]) { tv2[slot] = s; }
                    }
            }
        __syncthreads();   // sCn reused next nt
    }

    // reduce top-2 across the 4 lanes of each quad (same rows, different cols)
#pragma unroll
    for (int off = 1; off <= 2; off <<= 1)
#pragma unroll
        for (int s = 0; s < 4; s++) {
            float ov1 = __shfl_xor_sync(0xffffffffu, tv1[s], off);
            float ov2 = __shfl_xor_sync(0xffffffffu, tv2[s], off);
            int   oi1 = __shfl_xor_sync(0xffffffffu, ti1[s], off);
            top2_merge(tv1[s], ti1[s], tv2[s], ov1, oi1, ov2);
        }
    if (tg == 0) {
#pragma unroll
        for (int s = 0; s < 4; s++) {
            int row = wr * 32 + (s >> 1) * 16 + (s & 1) * 8 + gid;
            sV1[row * 4 + wc] = tv1[s];
            sV2[row * 4 + wc] = tv2[s];
            sI1[row * 4 + wc] = ti1[s];
        }
    }
    __syncthreads();

    if (tid < 128) {
        float v1 = sV1[tid * 4], v2 = sV2[tid * 4];
        int   i1 = sI1[tid * 4];
#pragma unroll
        for (int w = 1; w < 4; w++)
            top2_merge(v1, i1, v2, sV1[tid * 4 + w], sI1[tid * 4 + w], sV2[tid * 4 + w]);
        sBI[tid] = i1;
        if (v1 - v2 <= DELTA) {
            int p = atomicAdd(sUnN, 1);
            sUn[p] = tid;
        }
    }
    __syncthreads();

    // exact fp32 fallback for uncertain tokens (~2-4 per block)
    const float* ebk = books + (size_t)book * NEMB * DDIM;
    const int nUnc = *sUnN;
    for (int u = 0; u < nUnc; u++) {
        const int tk = sUn[u];
        if (tid < 256) sR[tid] = g_resid[(size_t)(tok0 + tk) * DDIM + tid];
        __syncthreads();
        float best = NEG_INF; int bi = 0;
        const float4* sR4 = (const float4*)sR;
#pragma unroll
        for (int e2 = 0; e2 < 2; e2++) {
            const int e = tid * 2 + e2;       // thread order == index order
            const float4* er = (const float4*)(ebk + (size_t)e * DDIM);
            float a = 0.f;
#pragma unroll 8
            for (int k = 0; k < 64; k++) {
                float4 x = sR4[k], y = er[k];
                a = fmaf(x.x, y.x, a); a = fmaf(x.y, y.y, a);
                a = fmaf(x.z, y.z, a); a = fmaf(x.w, y.w, a);
            }
            float s = a - cnb[e];
            if (s > best) { best = s; bi = e; }   // strict > keeps lowest e
        }
        sRV[tid] = best; sRI[tid] = bi;
        __syncthreads();
        // parallel reduce over 512 entries by warp 0, index tie-break
        if (wid == 0) {
            float v = sRV[lane]; int vi = sRI[lane];
#pragma unroll
            for (int j = 1; j < 16; j++) {
                float ov = sRV[lane + j * 32]; int oi = sRI[lane + j * 32];
                if (ov > v || (ov == v && oi < vi)) { v = ov; vi = oi; }
            }
#pragma unroll
            for (int off = 16; off; off >>= 1) {
                float ov = __shfl_xor_sync(0xffffffffu, v, off);
                int   oi = __shfl_xor_sync(0xffffffffu, vi, off);
                if (ov > v || (ov == v && oi < vi)) { v = ov; vi = oi; }
            }
            if (lane == 0) sBI[tk] = vi;
        }
        __syncthreads();
    }

    // residual update in place (exact fp32 codebook rows; L2-resident)
#pragma unroll 4
    for (int u = 0; u < 16; u++) {
        int i = tid + u * NTHREADS;
        int t = i >> 6, d4 = i & 63;
        int idx = sBI[t];
        float4 q = ((const float4*)(ebk + (size_t)idx * DDIM))[d4];
        float4* rp = ((float4*)(g_resid + (size_t)(tok0 + t) * DDIM)) + d4;
        float4 r = *rp;
        r.x -= q.x; r.y -= q.y; r.z -= q.z; r.w -= q.w;
        *rp = r;
    }
}

// ---------------------------------------------------------------------------
extern "C" void kernel_launch(void* const* d_in, const int* in_sizes, int n_in,
                              void* d_out, int out_size) {
    const float* z     = (const float*)d_in[0];
    const float* books = (const float*)d_in[1];
    const int*   nbu   = (const int*)d_in[2];
    float*       out   = (float*)d_out;

    cudaFuncSetAttribute(vq_step_mma, cudaFuncAttributeMaxDynamicSharedMemorySize, SMEM_TC);

    dim3 tgrid(TDIM / 32, DDIM / 32, BDIM);
    dim3 tblk(32, 8);

    init_resid<<<tgrid, tblk>>>(z);
    prep_books<<<(NBOOKS * NEMB) / 8, 256>>>(books);
    for (int k = 0; k < NBOOKS; k++)
        vq_step_mma<<<NTOK / 128, NTHREADS, SMEM_TC>>>(books, nbu, k);
    write_out<<<tgrid, tblk>>>(z, out);
}

// round 12
// speedup vs baseline: 2.0957x; 2.0957x over previous
#include <cuda_runtime.h>
#include <cuda_fp16.h>
#include <cstdint>

// Problem constants
#define BDIM   16
#define DDIM   256
#define TDIM   4096
#define NTOK   (BDIM * TDIM)   // 65536
#define NEMB   1024
#define NBOOKS 8

#define NEG_INF (-3.0e38f)
#define DELTA   2.0e-3f        // ~7 sigma of dropped Ah*Bl (fp16 split)

// Scratch
__device__ float g_resid[NTOK * DDIM];                  // 64 MB residual (N, D)
__device__ float g_cn[NBOOKS * NEMB];                   // 0.5*||e||^2
// fp16 codebooks (hi only), row-major [book][emb][k=256]
__device__ __half g_bh[NBOOKS * NEMB * DDIM];           // 4 MB

// ---------------------------------------------------------------------------
// helpers
// ---------------------------------------------------------------------------
__device__ __forceinline__ uint32_t smem_u32(const void* p) {
    uint32_t a;
    asm("{ .reg .u64 t; cvta.to.shared.u64 t, %1; cvt.u32.u64 %0, t; }" : "=r"(a) : "l"(p));
    return a;
}

#define LDSM4(r, addr)                                                         \
    asm volatile("ldmatrix.sync.aligned.m8n8.x4.shared.b16 {%0,%1,%2,%3}, [%4];" \
        : "=r"((r)[0]), "=r"((r)[1]), "=r"((r)[2]), "=r"((r)[3]) : "r"(addr))

#define MMA_F16(d, a, b0, b1)                                                  \
    asm volatile("mma.sync.aligned.m16n8k16.row.col.f32.f16.f16.f32 "          \
        "{%0,%1,%2,%3}, {%4,%5,%6,%7}, {%8,%9}, {%0,%1,%2,%3};"                \
        : "+f"((d)[0]), "+f"((d)[1]), "+f"((d)[2]), "+f"((d)[3])               \
        : "r"((a)[0]), "r"((a)[1]), "r"((a)[2]), "r"((a)[3]), "r"(b0), "r"(b1))

#define CP16(dst, src) asm volatile("cp.async.cg.shared.global [%0], [%1], 16;" :: "r"(dst), "l"(src))
#define CP_COMMIT()    asm volatile("cp.async.commit_group;" ::: "memory")
#define CP_WAIT1()     asm volatile("cp.async.wait_group 1;" ::: "memory")
#define CP_WAIT0()     asm volatile("cp.async.wait_group 0;" ::: "memory")

// fp16 hi/lo split of a float pair, packed low-first (consecutive k)
__device__ __forceinline__ void splitpack_h(float a, float b, uint32_t& hi, uint32_t& lo) {
    __half ah = __float2half_rn(a), bh = __float2half_rn(b);
    __half al = __float2half_rn(a - __half2float(ah));
    __half bl = __float2half_rn(b - __half2float(bh));
    __half2 h2 = __halves2half2(ah, bh);
    __half2 l2 = __halves2half2(al, bl);
    hi = *reinterpret_cast<uint32_t*>(&h2);
    lo = *reinterpret_cast<uint32_t*>(&l2);
}
__device__ __forceinline__ uint32_t pack_h2(float a, float b) {
    __half2 h2 = __halves2half2(__float2half_rn(a), __float2half_rn(b));
    return *reinterpret_cast<uint32_t*>(&h2);
}

__device__ __forceinline__ void top2_merge(float& v1, int& i1, float& v2,
                                           float ov1, int oi1, float ov2) {
    if (ov1 > v1) { v2 = fmaxf(v1, ov2); v1 = ov1; i1 = oi1; }
    else          { v2 = fmaxf(v2, ov1); }
}

// ---------------------------------------------------------------------------
// transpose init / finish kernels (proven)
// ---------------------------------------------------------------------------
__global__ void init_resid(const float* __restrict__ z) {
    __shared__ float tile[32][33];
    const int b = blockIdx.z, d0 = blockIdx.y * 32, t0 = blockIdx.x * 32;
    const int tx = threadIdx.x, ty = threadIdx.y;
#pragma unroll
    for (int j = 0; j < 32; j += 8)
        tile[ty + j][tx] = z[(b * DDIM + d0 + ty + j) * TDIM + t0 + tx];
    __syncthreads();
#pragma unroll
    for (int j = 0; j < 32; j += 8)
        g_resid[(b * TDIM + t0 + ty + j) * DDIM + d0 + tx] = tile[tx][ty + j];
}

__global__ void write_out(const float* __restrict__ z, float* __restrict__ out) {
    __shared__ float tile[32][33];
    const int b = blockIdx.z, d0 = blockIdx.y * 32, t0 = blockIdx.x * 32;
    const int tx = threadIdx.x, ty = threadIdx.y;
#pragma unroll
    for (int j = 0; j < 32; j += 8)
        tile[ty + j][tx] = g_resid[(b * TDIM + t0 + ty + j) * DDIM + d0 + tx];
    __syncthreads();
#pragma unroll
    for (int j = 0; j < 32; j += 8) {
        int zi = (b * DDIM + d0 + ty + j) * TDIM + t0 + tx;
        out[zi] = z[zi] - tile[tx][ty + j];
    }
}

// per-embedding half squared norms + fp16 pack (1 warp = 1 embed row)
__global__ void prep_books(const float* __restrict__ books) {
    const int row  = blockIdx.x * 8 + (threadIdx.x >> 5);   // 0..8191
    const int lane = threadIdx.x & 31;
    const float4* er4 = (const float4*)(books + (size_t)row * DDIM);
    float4 v0 = er4[lane * 2];
    float4 v1 = er4[lane * 2 + 1];
    float s = v0.x*v0.x + v0.y*v0.y + v0.z*v0.z + v0.w*v0.w
            + v1.x*v1.x + v1.y*v1.y + v1.z*v1.z + v1.w*v1.w;
#pragma unroll
    for (int off = 16; off; off >>= 1) s += __shfl_xor_sync(0xffffffffu, s, off);
    if (lane == 0) g_cn[row] = 0.5f * s;

    uint4 H;
    H.x = pack_h2(v0.x, v0.y);
    H.y = pack_h2(v0.z, v0.w);
    H.z = pack_h2(v1.x, v1.y);
    H.w = pack_h2(v1.z, v1.w);
    *(uint4*)(g_bh + (size_t)row * DDIM + lane * 8) = H;
}

// ---------------------------------------------------------------------------
// Fused VQ step on mma.sync (HMMA fp16): 2-term split GEMM + argmax + fallback
//   score ~= Ah*Bh + Al*Bh   (fp16 split; Ah*Bl dropped, margin ~7 sigma)
// 512 threads = 16 warps (4 token-rows x 4 embed-cols). CTA: 128 tok x 128 emb.
// ---------------------------------------------------------------------------
// smem byte layout.  A: 4 k-chunks of [128 rows][8 x 16B granules, swizzled]
#define OFF_AH   0                 // 64 KB
#define OFF_AL   65536             // 64 KB
#define OFF_B    131072            // 2 bufs x 16KB (hi only)
#define OFF_CN   163840            // 128 f
#define OFF_V1   164352            // 512 f
#define OFF_V2   166400            // 512 f
#define OFF_I1   168448            // 512 i
#define OFF_BI   170496            // 128 i
#define OFF_UNC  171008            // 4 + 128 i
#define OFF_SR   171536            // 256 f
#define OFF_RV   172560            // 512 f
#define OFF_RI   174608            // 512 i
#define SMEM_TC  176656

#define NTHREADS 512

__device__ __forceinline__ void copy_b_chunk(uint32_t sbase, int book, int nt,
                                             int kc, int buf, int tid) {
    const __half* srcH = g_bh + ((size_t)(book * NEMB + nt * 128) * DDIM + kc * 64);
#pragma unroll
    for (int u = 0; u < 2; u++) {
        int idx = tid + u * NTHREADS;     // 1024 granules: 128 rows x 8
        int r = idx >> 3, g = idx & 7;
        uint32_t dst = sbase + OFF_B + buf * 16384 + r * 128 + ((g ^ (r & 7)) << 4);
        CP16(dst, srcH + (size_t)r * DDIM + g * 8);
    }
}

__global__ void __launch_bounds__(NTHREADS) vq_step_mma(const float* __restrict__ books,
                                                        const int* __restrict__ nbu,
                                                        int book) {
    if (book >= *nbu) return;
    extern __shared__ char smem[];
    const uint32_t sbase = smem_u32(smem);
    const int tid = threadIdx.x, lane = tid & 31, wid = tid >> 5;
    const int wr = wid & 3, wc = wid >> 2;           // 4 x 4 warp grid
    const int gid = lane >> 2, tg = lane & 3;
    const int tok0 = blockIdx.x * 128;

    float* sCn  = (float*)(smem + OFF_CN);
    float* sV1  = (float*)(smem + OFF_V1);
    float* sV2  = (float*)(smem + OFF_V2);
    int*   sI1  = (int*)(smem + OFF_I1);
    int*   sBI  = (int*)(smem + OFF_BI);
    int*   sUnN = (int*)(smem + OFF_UNC);
    int*   sUn  = (int*)(smem + OFF_UNC + 4);
    float* sR   = (float*)(smem + OFF_SR);
    float* sRV  = (float*)(smem + OFF_RV);
    int*   sRI  = (int*)(smem + OFF_RI);

    if (tid == 0) *sUnN = 0;

    // ---- stage A: residual 128 tok x 256 k, fp16 hi/lo split, swizzled ----
#pragma unroll 4
    for (int u = 0; u < 8; u++) {
        int idx = tid + u * NTHREADS;     // 4096 16B-units: 128 rows x 32
        int t = idx >> 5, gg = idx & 31;  // gg = k granule 0..31
        const float4* rr = (const float4*)(g_resid + (size_t)(tok0 + t) * DDIM);
        float4 a = rr[gg * 2], b = rr[gg * 2 + 1];
        uint4 H, L;
        splitpack_h(a.x, a.y, H.x, L.x);
        splitpack_h(a.z, a.w, H.y, L.y);
        splitpack_h(b.x, b.y, H.z, L.z);
        splitpack_h(b.z, b.w, H.w, L.w);
        int kc = gg >> 3, g = gg & 7;
        uint32_t off = kc * 16384 + t * 128 + ((g ^ (t & 7)) << 4);
        *(uint4*)(smem + OFF_AH + off) = H;
        *(uint4*)(smem + OFF_AL + off) = L;
    }
    __syncthreads();

    const float* cnb = g_cn + book * NEMB;

    // ldmatrix per-lane address components
    const int xsw = lane & 7;
    const int kg  = lane >> 4;
    const uint32_t aBase0 = sbase + OFF_AH + (wr * 32 +      (lane & 15)) * 128;
    const uint32_t aBase1 = sbase + OFF_AH + (wr * 32 + 16 + (lane & 15)) * 128;
    const uint32_t nb0 = (wc * 32 +      (lane & 15)) * 128;
    const uint32_t nb1 = (wc * 32 + 16 + (lane & 15)) * 128;

    float tv1[4], tv2[4];
    int   ti1[4];
#pragma unroll
    for (int s = 0; s < 4; s++) { tv1[s] = NEG_INF; tv2[s] = NEG_INF; ti1[s] = 0; }

    for (int nt = 0; nt < 8; nt++) {
        if (tid < 128) sCn[tid] = cnb[nt * 128 + tid];

        float acc[2][4][4];
#pragma unroll
        for (int mi = 0; mi < 2; mi++)
#pragma unroll
            for (int ni = 0; ni < 4; ni++)
#pragma unroll
                for (int q = 0; q < 4; q++) acc[mi][ni][q] = 0.f;

        copy_b_chunk(sbase, book, nt, 0, 0, tid);
        CP_COMMIT();

        for (int kc = 0; kc < 4; kc++) {
            if (kc < 3) {
                copy_b_chunk(sbase, book, nt, kc + 1, (kc + 1) & 1, tid);
                CP_COMMIT();
                CP_WAIT1();
            } else {
                CP_WAIT0();
            }
            __syncthreads();

            const uint32_t Akc = kc * 16384;
            const uint32_t Bb  = sbase + OFF_B + (kc & 1) * 16384;

#pragma unroll
            for (int ks = 0; ks < 4; ks++) {
                const int gsw = ((ks * 2 + kg) ^ xsw) << 4;
                uint32_t ah[2][4], al[2][4], bh[2][4];
                LDSM4(ah[0], aBase0 + Akc + gsw);
                LDSM4(bh[0], Bb + nb0 + gsw);
                LDSM4(bh[1], Bb + nb1 + gsw);
                LDSM4(ah[1], aBase1 + Akc + gsw);
                LDSM4(al[0], aBase0 + 65536 + Akc + gsw);   // OFF_AL = OFF_AH + 65536
                LDSM4(al[1], aBase1 + 65536 + Akc + gsw);

                // term-major: 8 independent MMAs per term
#pragma unroll
                for (int mi = 0; mi < 2; mi++)
#pragma unroll
                    for (int nb = 0; nb < 2; nb++)
#pragma unroll
                        for (int h = 0; h < 2; h++)
                            MMA_F16(acc[mi][nb * 2 + h], ah[mi], bh[nb][h], bh[nb][h + 2]);
#pragma unroll
                for (int mi = 0; mi < 2; mi++)
#pragma unroll
                    for (int nb = 0; nb < 2; nb++)
#pragma unroll
                        for (int h = 0; h < 2; h++)
                            MMA_F16(acc[mi][nb * 2 + h], al[mi], bh[nb][h], bh[nb][h + 2]);
            }
            __syncthreads();
        }

        // fold this nt's 32 scores/thread into per-row running top-2
#pragma unroll
        for (int mi = 0; mi < 2; mi++)
#pragma unroll
            for (int h = 0; h < 2; h++) {
                const int slot = mi * 2 + h;
#pragma unroll
                for (int ni = 0; ni < 4; ni++)
#pragma unroll
                    for (int c = 0; c < 2; c++) {
                        const int col = ni * 8 + tg * 2 + c;
                        float s = acc[mi][ni][h * 2 + c] - sCn[wc * 32 + col];
                        int  ii = nt * 128 + wc * 32 + col;
                        if (s > tv1[slot]) { tv2[slot] = tv1[slot]; tv1[slot] = s; ti1[slot] = ii; }
                        else if (s > tv2[slot]) { tv2[slot] = s; }
                    }
            }
        __syncthreads();   // sCn reused next nt
    }

    // reduce top-2 across the 4 lanes of each quad (same rows, different cols)
#pragma unroll
    for (int off = 1; off <= 2; off <<= 1)
#pragma unroll
        for (int s = 0; s < 4; s++) {
            float ov1 = __shfl_xor_sync(0xffffffffu, tv1[s], off);
            float ov2 = __shfl_xor_sync(0xffffffffu, tv2[s], off);
            int   oi1 = __shfl_xor_sync(0xffffffffu, ti1[s], off);
            top2_merge(tv1[s], ti1[s], tv2[s], ov1, oi1, ov2);
        }
    if (tg == 0) {
#pragma unroll
        for (int s = 0; s < 4; s++) {
            int row = wr * 32 + (s >> 1) * 16 + (s & 1) * 8 + gid;
            sV1[row * 4 + wc] = tv1[s];
            sV2[row * 4 + wc] = tv2[s];
            sI1[row * 4 + wc] = ti1[s];
        }
    }
    __syncthreads();

    if (tid < 128) {
        float v1 = sV1[tid * 4], v2 = sV2[tid * 4];
        int   i1 = sI1[tid * 4];
#pragma unroll
        for (int w = 1; w < 4; w++)
            top2_merge(v1, i1, v2, sV1[tid * 4 + w], sI1[tid * 4 + w], sV2[tid * 4 + w]);
        sBI[tid] = i1;
        if (v1 - v2 <= DELTA) {
            int p = atomicAdd(sUnN, 1);
            sUn[p] = tid;
        }
    }
    __syncthreads();

    // exact fp32 fallback for uncertain tokens (rare: ~1-3 per block)
    const float* ebk = books + (size_t)book * NEMB * DDIM;
    const int nUnc = *sUnN;
    for (int u = 0; u < nUnc; u++) {
        const int tk = sUn[u];
        if (tid < 256) sR[tid] = g_resid[(size_t)(tok0 + tk) * DDIM + tid];
        __syncthreads();
        float best = NEG_INF; int bi = 0;
        const float4* sR4 = (const float4*)sR;
#pragma unroll
        for (int e2 = 0; e2 < 2; e2++) {
            const int e = tid * 2 + e2;       // thread order == index order
            const float4* er = (const float4*)(ebk + (size_t)e * DDIM);
            float a = 0.f;
#pragma unroll 8
            for (int k = 0; k < 64; k++) {
                float4 x = sR4[k], y = er[k];
                a = fmaf(x.x, y.x, a); a = fmaf(x.y, y.y, a);
                a = fmaf(x.z, y.z, a); a = fmaf(x.w, y.w, a);
            }
            float s = a - cnb[e];
            if (s > best) { best = s; bi = e; }   // strict > keeps lowest e
        }
        sRV[tid] = best; sRI[tid] = bi;
        __syncthreads();
        // parallel reduce over 512 entries by warp 0, index tie-break
        if (wid == 0) {
            float v = sRV[lane]; int vi = sRI[lane];
#pragma unroll
            for (int j = 1; j < 16; j++) {
                float ov = sRV[lane + j * 32]; int oi = sRI[lane + j * 32];
                if (ov > v || (ov == v && oi < vi)) { v = ov; vi = oi; }
            }
#pragma unroll
            for (int off = 16; off; off >>= 1) {
                float ov = __shfl_xor_sync(0xffffffffu, v, off);
                int   oi = __shfl_xor_sync(0xffffffffu, vi, off);
                if (ov > v || (ov == v && oi < vi)) { v = ov; vi = oi; }
            }
            if (lane == 0) sBI[tk] = vi;
        }
        __syncthreads();
    }

    // residual update in place (exact fp32 codebook rows; L2-resident)
#pragma unroll 4
    for (int u = 0; u < 16; u++) {
        int i = tid + u * NTHREADS;
        int t = i >> 6, d4 = i & 63;
        int idx = sBI[t];
        float4 q = ((const float4*)(ebk + (size_t)idx * DDIM))[d4];
        float4* rp = ((float4*)(g_resid + (size_t)(tok0 + t) * DDIM)) + d4;
        float4 r = *rp;
        r.x -= q.x; r.y -= q.y; r.z -= q.z; r.w -= q.w;
        *rp = r;
    }
}

// ---------------------------------------------------------------------------
extern "C" void kernel_launch(void* const* d_in, const int* in_sizes, int n_in,
                              void* d_out, int out_size) {
    const float* z     = (const float*)d_in[0];
    const float* books = (const float*)d_in[1];
    const int*   nbu   = (const int*)d_in[2];
    float*       out   = (float*)d_out;

    cudaFuncSetAttribute(vq_step_mma, cudaFuncAttributeMaxDynamicSharedMemorySize, SMEM_TC);

    dim3 tgrid(TDIM / 32, DDIM / 32, BDIM);
    dim3 tblk(32, 8);

    init_resid<<<tgrid, tblk>>>(z);
    prep_books<<<(NBOOKS * NEMB) / 8, 256>>>(books);
    for (int k = 0; k < NBOOKS; k++)
        vq_step_mma<<<NTOK / 128, NTHREADS, SMEM_TC>>>(books, nbu, k);
    write_out<<<tgrid, tblk>>>(z, out);
}

// round 13
// speedup vs baseline: 2.2753x; 1.0857x over previous
#include <cuda_runtime.h>
#include <cuda_fp16.h>
#include <cstdint>

// Problem constants
#define BDIM   16
#define DDIM   256
#define TDIM   4096
#define NTOK   (BDIM * TDIM)   // 65536
#define NEMB   1024
#define NBOOKS 8

#define NEG_INF (-3.0e38f)
#define DELTA   2.0e-3f        // ~7 sigma of dropped Ah*Bl (fp16 split)

// Scratch
__device__ float g_resid[NTOK * DDIM];                  // 64 MB residual (N, D)
__device__ float g_cn[NBOOKS * NEMB];                   // 0.5*||e||^2
// fp16 codebooks (hi only), row-major [book][emb][k=256]
__device__ __half g_bh[NBOOKS * NEMB * DDIM];           // 4 MB

// ---------------------------------------------------------------------------
// helpers
// ---------------------------------------------------------------------------
__device__ __forceinline__ uint32_t smem_u32(const void* p) {
    uint32_t a;
    asm("{ .reg .u64 t; cvta.to.shared.u64 t, %1; cvt.u32.u64 %0, t; }" : "=r"(a) : "l"(p));
    return a;
}

#define LDSM4(r, addr)                                                         \
    asm volatile("ldmatrix.sync.aligned.m8n8.x4.shared.b16 {%0,%1,%2,%3}, [%4];" \
        : "=r"((r)[0]), "=r"((r)[1]), "=r"((r)[2]), "=r"((r)[3]) : "r"(addr))

#define MMA_F16(d, a, b0, b1)                                                  \
    asm volatile("mma.sync.aligned.m16n8k16.row.col.f32.f16.f16.f32 "          \
        "{%0,%1,%2,%3}, {%4,%5,%6,%7}, {%8,%9}, {%0,%1,%2,%3};"                \
        : "+f"((d)[0]), "+f"((d)[1]), "+f"((d)[2]), "+f"((d)[3])               \
        : "r"((a)[0]), "r"((a)[1]), "r"((a)[2]), "r"((a)[3]), "r"(b0), "r"(b1))

#define CP16(dst, src) asm volatile("cp.async.cg.shared.global [%0], [%1], 16;" :: "r"(dst), "l"(src))
#define CP_COMMIT()    asm volatile("cp.async.commit_group;" ::: "memory")
#define CP_WAIT0()     asm volatile("cp.async.wait_group 0;" ::: "memory")

// swizzle: 16B granule g (0..31) within a 512B row, row r
__device__ __forceinline__ int swzg(int g, int r) {
    return (((g & 24) | ((g & 7) ^ (r & 7)))) << 4;
}

// fp16 hi/lo split of a float pair, packed low-first (consecutive k)
__device__ __forceinline__ void splitpack_h(float a, float b, uint32_t& hi, uint32_t& lo) {
    __half ah = __float2half_rn(a), bh = __float2half_rn(b);
    __half al = __float2half_rn(a - __half2float(ah));
    __half bl = __float2half_rn(b - __half2float(bh));
    __half2 h2 = __halves2half2(ah, bh);
    __half2 l2 = __halves2half2(al, bl);
    hi = *reinterpret_cast<uint32_t*>(&h2);
    lo = *reinterpret_cast<uint32_t*>(&l2);
}
__device__ __forceinline__ uint32_t pack_h2(float a, float b) {
    __half2 h2 = __halves2half2(__float2half_rn(a), __float2half_rn(b));
    return *reinterpret_cast<uint32_t*>(&h2);
}

__device__ __forceinline__ void top2_merge(float& v1, int& i1, float& v2,
                                           float ov1, int oi1, float ov2) {
    if (ov1 > v1) { v2 = fmaxf(v1, ov2); v1 = ov1; i1 = oi1; }
    else          { v2 = fmaxf(v2, ov1); }
}

// ---------------------------------------------------------------------------
// transpose init / finish kernels (proven)
// ---------------------------------------------------------------------------
__global__ void init_resid(const float* __restrict__ z) {
    __shared__ float tile[32][33];
    const int b = blockIdx.z, d0 = blockIdx.y * 32, t0 = blockIdx.x * 32;
    const int tx = threadIdx.x, ty = threadIdx.y;
#pragma unroll
    for (int j = 0; j < 32; j += 8)
        tile[ty + j][tx] = z[(b * DDIM + d0 + ty + j) * TDIM + t0 + tx];
    __syncthreads();
#pragma unroll
    for (int j = 0; j < 32; j += 8)
        g_resid[(b * TDIM + t0 + ty + j) * DDIM + d0 + tx] = tile[tx][ty + j];
}

__global__ void write_out(const float* __restrict__ z, float* __restrict__ out) {
    __shared__ float tile[32][33];
    const int b = blockIdx.z, d0 = blockIdx.y * 32, t0 = blockIdx.x * 32;
    const int tx = threadIdx.x, ty = threadIdx.y;
#pragma unroll
    for (int j = 0; j < 32; j += 8)
        tile[ty + j][tx] = g_resid[(b * TDIM + t0 + ty + j) * DDIM + d0 + tx];
    __syncthreads();
#pragma unroll
    for (int j = 0; j < 32; j += 8) {
        int zi = (b * DDIM + d0 + ty + j) * TDIM + t0 + tx;
        out[zi] = z[zi] - tile[tx][ty + j];
    }
}

// per-embedding half squared norms + fp16 pack (1 warp = 1 embed row)
__global__ void prep_books(const float* __restrict__ books) {
    const int row  = blockIdx.x * 8 + (threadIdx.x >> 5);   // 0..8191
    const int lane = threadIdx.x & 31;
    const float4* er4 = (const float4*)(books + (size_t)row * DDIM);
    float4 v0 = er4[lane * 2];
    float4 v1 = er4[lane * 2 + 1];
    float s = v0.x*v0.x + v0.y*v0.y + v0.z*v0.z + v0.w*v0.w
            + v1.x*v1.x + v1.y*v1.y + v1.z*v1.z + v1.w*v1.w;
#pragma unroll
    for (int off = 16; off; off >>= 1) s += __shfl_xor_sync(0xffffffffu, s, off);
    if (lane == 0) g_cn[row] = 0.5f * s;

    uint4 H;
    H.x = pack_h2(v0.x, v0.y);
    H.y = pack_h2(v0.z, v0.w);
    H.z = pack_h2(v1.x, v1.y);
    H.w = pack_h2(v1.z, v1.w);
    *(uint4*)(g_bh + (size_t)row * DDIM + lane * 8) = H;
}

// ---------------------------------------------------------------------------
// Fused VQ step on mma.sync (fp16): 2-term split GEMM + argmax + fallback
//   score ~= Ah*Bh + Al*Bh   (fp16 split; Ah*Bl dropped, margin ~7 sigma)
// 512 threads = 16 warps (4 token-rows x 4 embed-cols). CTA: 64 tok x 128 emb.
// Full-K B tiles: 8 stages/CTA, 1 barrier pair + 16 k-steps per stage.
// ---------------------------------------------------------------------------
// smem byte layout.  rows are 512B (k-major, full K=256 fp16), swizzled
#define OFF_AH   0                 // 32 KB: 64 rows x 512B
#define OFF_AL   32768             // 32 KB
#define OFF_B    65536             // 2 bufs x 64KB: 128 rows x 512B
#define OFF_CN   196608            // 2 x 128 f
#define OFF_V1   197632            // 512 f
#define OFF_V2   199680            // 512 f
#define OFF_I1   201728            // 512 i
#define OFF_BI   203776            // 64 i (pad)
#define OFF_UNC  204032            // 4 + 64 i (pad)
#define OFF_SR   204304            // 256 f
#define OFF_RV   205328            // 512 f
#define OFF_RI   207376            // 512 i
#define SMEM_TC  209424

#define NTHREADS 512
#define TOK_CTA  64

__device__ __forceinline__ void copy_b_nt(uint32_t sbase, int book, int nt,
                                          int buf, int tid) {
    const __half* srcH = g_bh + (size_t)(book * NEMB + nt * 128) * DDIM;
#pragma unroll
    for (int u = 0; u < 8; u++) {
        int idx = tid + u * NTHREADS;     // 4096 granules: 128 rows x 32
        int r = idx >> 5, g = idx & 31;
        uint32_t dst = sbase + OFF_B + buf * 65536 + r * 512 + swzg(g, r);
        CP16(dst, srcH + (size_t)r * DDIM + g * 8);
    }
}

__global__ void __launch_bounds__(NTHREADS) vq_step_mma(const float* __restrict__ books,
                                                        const int* __restrict__ nbu,
                                                        int book) {
    if (book >= *nbu) return;
    extern __shared__ char smem[];
    const uint32_t sbase = smem_u32(smem);
    const int tid = threadIdx.x, lane = tid & 31, wid = tid >> 5;
    const int wr = wid & 3, wc = wid >> 2;           // 4 x 4 warp grid
    const int gid = lane >> 2, tg = lane & 3;
    const int tok0 = blockIdx.x * TOK_CTA;

    float* sCn  = (float*)(smem + OFF_CN);
    float* sV1  = (float*)(smem + OFF_V1);
    float* sV2  = (float*)(smem + OFF_V2);
    int*   sI1  = (int*)(smem + OFF_I1);
    int*   sBI  = (int*)(smem + OFF_BI);
    int*   sUnN = (int*)(smem + OFF_UNC);
    int*   sUn  = (int*)(smem + OFF_UNC + 4);
    float* sR   = (float*)(smem + OFF_SR);
    float* sRV  = (float*)(smem + OFF_RV);
    int*   sRI  = (int*)(smem + OFF_RI);

    if (tid == 0) *sUnN = 0;

    const float* cnb = g_cn + book * NEMB;

    // prologue: kick off B copy for stage 0, then stage A while it flies
    copy_b_nt(sbase, book, 0, 0, tid);
    CP_COMMIT();

    // ---- stage A: residual 64 tok x 256 k, fp16 hi/lo split, swizzled ----
#pragma unroll
    for (int u = 0; u < 4; u++) {
        int idx = tid + u * NTHREADS;     // 2048 16B-units: 64 rows x 32
        int t = idx >> 5, gg = idx & 31;
        const float4* rr = (const float4*)(g_resid + (size_t)(tok0 + t) * DDIM);
        float4 a = rr[gg * 2], b = rr[gg * 2 + 1];
        uint4 H, L;
        splitpack_h(a.x, a.y, H.x, L.x);
        splitpack_h(a.z, a.w, H.y, L.y);
        splitpack_h(b.x, b.y, H.z, L.z);
        splitpack_h(b.z, b.w, H.w, L.w);
        uint32_t off = t * 512 + swzg(gg, t);
        *(uint4*)(smem + OFF_AH + off) = H;
        *(uint4*)(smem + OFF_AL + off) = L;
    }
    if (tid < 128) sCn[tid] = cnb[tid];   // norms for nt=0 (buffer 0)

    // ldmatrix per-lane address components
    const int xsw = lane & 7;
    const int kg  = lane >> 4;
    const uint32_t aBaseH = sbase + OFF_AH + (wr * 16 + (lane & 15)) * 512;
    const uint32_t bRow0  = (wc * 32 +      (lane & 15)) * 512;
    const uint32_t bRow1  = (wc * 32 + 16 + (lane & 15)) * 512;

    float tv1[2], tv2[2];
    int   ti1[2];
#pragma unroll
    for (int s = 0; s < 2; s++) { tv1[s] = NEG_INF; tv2[s] = NEG_INF; ti1[s] = 0; }

    // ---- 8-stage mainloop: 1 barrier pair + 16 k-steps per stage ----
    for (int nt = 0; nt < 8; nt++) {
        CP_WAIT0();          // B(nt) landed (only pending group)
        __syncthreads();     // B(nt), sCn(nt) visible; all done with stage nt-1

        if (nt + 1 < 8) {
            copy_b_nt(sbase, book, nt + 1, (nt + 1) & 1, tid);
            CP_COMMIT();
            if (tid < 128) sCn[((nt + 1) & 1) * 128 + tid] = cnb[(nt + 1) * 128 + tid];
        }

        float acc[4][4];
#pragma unroll
        for (int nbh = 0; nbh < 4; nbh++)
#pragma unroll
            for (int q = 0; q < 4; q++) acc[nbh][q] = 0.f;

        const uint32_t Bb = sbase + OFF_B + (nt & 1) * 65536;

#pragma unroll
        for (int ks = 0; ks < 16; ks++) {
            const int g = ks * 2 + kg;
            const int gsw = ((g & 24) | ((g & 7) ^ xsw)) << 4;
            uint32_t ah[4], al[4], bh0[4], bh1[4];
            LDSM4(ah,  aBaseH + gsw);
            LDSM4(bh0, Bb + bRow0 + gsw);
            LDSM4(bh1, Bb + bRow1 + gsw);
            LDSM4(al,  aBaseH + 32768 + gsw);   // OFF_AL = OFF_AH + 32768

            // term-major: 4 independent MMAs per term
            MMA_F16(acc[0], ah, bh0[0], bh0[2]);
            MMA_F16(acc[1], ah, bh0[1], bh0[3]);
            MMA_F16(acc[2], ah, bh1[0], bh1[2]);
            MMA_F16(acc[3], ah, bh1[1], bh1[3]);
            MMA_F16(acc[0], al, bh0[0], bh0[2]);
            MMA_F16(acc[1], al, bh0[1], bh0[3]);
            MMA_F16(acc[2], al, bh1[0], bh1[2]);
            MMA_F16(acc[3], al, bh1[1], bh1[3]);
        }

        // fold this nt's 16 scores/thread into per-row running top-2
        const float* cn = sCn + (nt & 1) * 128 + wc * 32;
#pragma unroll
        for (int rh = 0; rh < 2; rh++)
#pragma unroll
            for (int nbh = 0; nbh < 4; nbh++)
#pragma unroll
                for (int c = 0; c < 2; c++) {
                    const int col = (nbh >> 1) * 16 + (nbh & 1) * 8 + tg * 2 + c;
                    float s = acc[nbh][rh * 2 + c] - cn[col];
                    int  ii = nt * 128 + wc * 32 + col;
                    if (s > tv1[rh]) { tv2[rh] = tv1[rh]; tv1[rh] = s; ti1[rh] = ii; }
                    else if (s > tv2[rh]) { tv2[rh] = s; }
                }
    }

    // reduce top-2 across the 4 lanes of each quad (same rows, different cols)
#pragma unroll
    for (int off = 1; off <= 2; off <<= 1)
#pragma unroll
        for (int s = 0; s < 2; s++) {
            float ov1 = __shfl_xor_sync(0xffffffffu, tv1[s], off);
            float ov2 = __shfl_xor_sync(0xffffffffu, tv2[s], off);
            int   oi1 = __shfl_xor_sync(0xffffffffu, ti1[s], off);
            top2_merge(tv1[s], ti1[s], tv2[s], ov1, oi1, ov2);
        }
    __syncthreads();   // all stages done before sV writes reuse smem timeline
    if (tg == 0) {
#pragma unroll
        for (int s = 0; s < 2; s++) {
            int row = wr * 16 + s * 8 + gid;
            sV1[row * 8 + wc * 2]     = tv1[s];   // stride-8 rows, 4 col-warps
            sV2[row * 8 + wc * 2]     = tv2[s];
            sI1[row * 8 + wc * 2]     = ti1[s];
        }
    }
    __syncthreads();

    if (tid < TOK_CTA) {
        float v1 = sV1[tid * 8], v2 = sV2[tid * 8];
        int   i1 = sI1[tid * 8];
#pragma unroll
        for (int w = 1; w < 4; w++)
            top2_merge(v1, i1, v2, sV1[tid * 8 + w * 2], sI1[tid * 8 + w * 2], sV2[tid * 8 + w * 2]);
        sBI[tid] = i1;
        if (v1 - v2 <= DELTA) {
            int p = atomicAdd(sUnN, 1);
            sUn[p] = tid;
        }
    }
    __syncthreads();

    // exact fp32 fallback for uncertain tokens (rare: ~1 per block)
    const float* ebk = books + (size_t)book * NEMB * DDIM;
    const int nUnc = *sUnN;
    for (int u = 0; u < nUnc; u++) {
        const int tk = sUn[u];
        if (tid < 256) sR[tid] = g_resid[(size_t)(tok0 + tk) * DDIM + tid];
        __syncthreads();
        float best = NEG_INF; int bi = 0;
        const float4* sR4 = (const float4*)sR;
#pragma unroll
        for (int e2 = 0; e2 < 2; e2++) {
            const int e = tid * 2 + e2;       // thread order == index order
            const float4* er = (const float4*)(ebk + (size_t)e * DDIM);
            float a = 0.f;
#pragma unroll 8
            for (int k = 0; k < 64; k++) {
                float4 x = sR4[k], y = er[k];
                a = fmaf(x.x, y.x, a); a = fmaf(x.y, y.y, a);
                a = fmaf(x.z, y.z, a); a = fmaf(x.w, y.w, a);
            }
            float s = a - cnb[e];
            if (s > best) { best = s; bi = e; }   // strict > keeps lowest e
        }
        sRV[tid] = best; sRI[tid] = bi;
        __syncthreads();
        // parallel reduce over 512 entries by warp 0, index tie-break
        if (wid == 0) {
            float v = sRV[lane]; int vi = sRI[lane];
#pragma unroll
            for (int j = 1; j < 16; j++) {
                float ov = sRV[lane + j * 32]; int oi = sRI[lane + j * 32];
                if (ov > v || (ov == v && oi < vi)) { v = ov; vi = oi; }
            }
#pragma unroll
            for (int off = 16; off; off >>= 1) {
                float ov = __shfl_xor_sync(0xffffffffu, v, off);
                int   oi = __shfl_xor_sync(0xffffffffu, vi, off);
                if (ov > v || (ov == v && oi < vi)) { v = ov; vi = oi; }
            }
            if (lane == 0) sBI[tk] = vi;
        }
        __syncthreads();
    }

    // residual update in place (exact fp32 codebook rows; L2-resident)
#pragma unroll
    for (int u = 0; u < 8; u++) {
        int i = tid + u * NTHREADS;       // 4096 = 64 tok x 64 float4
        int t = i >> 6, d4 = i & 63;
        int idx = sBI[t];
        float4 q = ((const float4*)(ebk + (size_t)idx * DDIM))[d4];
        float4* rp = ((float4*)(g_resid + (size_t)(tok0 + t) * DDIM)) + d4;
        float4 r = *rp;
        r.x -= q.x; r.y -= q.y; r.z -= q.z; r.w -= q.w;
        *rp = r;
    }
}

// ---------------------------------------------------------------------------
extern "C" void kernel_launch(void* const* d_in, const int* in_sizes, int n_in,
                              void* d_out, int out_size) {
    const float* z     = (const float*)d_in[0];
    const float* books = (const float*)d_in[1];
    const int*   nbu   = (const int*)d_in[2];
    float*       out   = (float*)d_out;

    cudaFuncSetAttribute(vq_step_mma, cudaFuncAttributeMaxDynamicSharedMemorySize, SMEM_TC);

    dim3 tgrid(TDIM / 32, DDIM / 32, BDIM);
    dim3 tblk(32, 8);

    init_resid<<<tgrid, tblk>>>(z);
    prep_books<<<(NBOOKS * NEMB) / 8, 256>>>(books);
    for (int k = 0; k < NBOOKS; k++)
        vq_step_mma<<<NTOK / TOK_CTA, NTHREADS, SMEM_TC>>>(books, nbu, k);
    write_out<<<tgrid, tblk>>>(z, out);
}